// round 12
// baseline (speedup 1.0000x reference)
#include <cuda_runtime.h>
#include <math.h>
#include <stdint.h>

// ---------------------------------------------------------------------------
// SPFBlock fused kernel v6, sm_103 (portable PTX) — mma.sync m16n8k8 tf32.
// v6: k_main at 512 threads / 16 warps (was 256/8): halves per-warp mma chain,
// doubles issue parallelism at the same smem footprint (126 KB, 1 block/SM).
// ---------------------------------------------------------------------------

#define BATCH   4
#define CIN     128
#define LTOT    16384
#define NHEAD   4
#define NPH     32
#define MTRI    528
#define CPOOL   2112
#define DIMO    64
#define NCHUNK  33              // 33 * 64 = 2112

// smem float offsets (k_main)
#define FT      0               // t tile [128c][128p]              16384
#define FPF     16384           // pf [64k][136] (later zt[128][68])  8704
#define FB      25088           // B  [64k][72]                       4608
#define FS      29696           // scales 512
#define FP      30208           // params 256
#define FIJ     30464           // ij table 4224 B = 1056 floats
#define FTOT    31520           // 126080 bytes

// ------------------------- device scratch (static) -------------------------
__device__ float g_t[BATCH * CIN * LTOT];       // shuffled LN'd t, [b][c][pos]
__device__ float g_e[BATCH * LTOT * NHEAD];     // exp(logit)
__device__ float g_wTk[CPOOL * DIMO];           // dr_w, k-major, tf32-rounded
__device__ float g_fc1T[DIMO * DIMO];           // fc1_w transposed [c][j]
__device__ float g_umid[BATCH * CIN];
__device__ float g_invnmid[BATCH * NHEAD];
__device__ float g_sumexp[BATCH * NHEAD];
__device__ uchar2 g_ij[CPOOL];

// ------------------------------ PTX helpers --------------------------------
__device__ __forceinline__ uint32_t cvt_tf32(float x) {
    uint32_t r;
    asm("cvt.rna.tf32.f32 %0, %1;" : "=r"(r) : "f"(x));
    return r;
}
__device__ __forceinline__ void mma8(float* d, const uint32_t* a, const uint32_t* b) {
    asm volatile(
        "mma.sync.aligned.m16n8k8.row.col.f32.tf32.tf32.f32 "
        "{%0,%1,%2,%3}, {%4,%5,%6,%7}, {%8,%9}, {%0,%1,%2,%3};"
        : "+f"(d[0]), "+f"(d[1]), "+f"(d[2]), "+f"(d[3])
        : "r"(a[0]), "r"(a[1]), "r"(a[2]), "r"(a[3]), "r"(b[0]), "r"(b[1]));
}

// ------------------------------- init kernel -------------------------------
__global__ void k_init(const float* __restrict__ dr_w,
                       const float* __restrict__ fc1_w) {
    int tid = blockIdx.x * blockDim.x + threadIdx.x;
    int nth = gridDim.x * blockDim.x;
    for (int idx = tid; idx < CPOOL * DIMO; idx += nth) {
        int k = idx >> 6, o = idx & 63;
        g_wTk[idx] = __uint_as_float(cvt_tf32(dr_w[o * CPOOL + k]));
    }
    for (int idx = tid; idx < DIMO * DIMO; idx += nth) {
        int c = idx >> 6, j = idx & 63;
        g_fc1T[idx] = fc1_w[j * DIMO + c];
    }
    if (blockIdx.x == 0) {
        for (int m = threadIdx.x; m < MTRI; m += blockDim.x) {
            int i = 0, off = 0;
            while (off + (NPH - i) <= m) { off += NPH - i; i++; }
            int j = i + (m - off);
            #pragma unroll
            for (int h = 0; h < NHEAD; h++) {
                uchar2 v;
                v.x = (unsigned char)(h * NPH + i);
                v.y = (unsigned char)(h * NPH + j);
                g_ij[h * MTRI + m] = v;
            }
        }
        if (threadIdx.x < BATCH * NHEAD) g_sumexp[threadIdx.x] = 0.0f;
    }
}

// ------------------------------- mid kernel --------------------------------
__global__ void k_mid(const float* __restrict__ x,
                      const float* __restrict__ n1w,
                      const float* __restrict__ n1b) {
    __shared__ float red[CIN];
    __shared__ float us[CIN];
    int b = blockIdx.x, tid = threadIdx.x;
    float v = x[((size_t)b * CIN + tid) * LTOT + (LTOT / 2)];
    red[tid] = v;
    __syncthreads();
    for (int o = 64; o; o >>= 1) { if (tid < o) red[tid] += red[tid + o]; __syncthreads(); }
    float mu = red[0] * (1.0f / 128.0f);
    __syncthreads();
    red[tid] = v * v;
    __syncthreads();
    for (int o = 64; o; o >>= 1) { if (tid < o) red[tid] += red[tid + o]; __syncthreads(); }
    float var = red[0] * (1.0f / 128.0f) - mu * mu;
    float rstd = rsqrtf(var + 1e-5f);
    float xn = (v - mu) * rstd * n1w[tid] + n1b[tid];
    int cp = ((tid & 3) << 5) + (tid >> 2);
    us[cp] = xn;
    g_umid[b * CIN + cp] = xn;
    __syncthreads();
    if (tid < NHEAD) {
        float uu = 0.f, s4 = 0.f;
        #pragma unroll
        for (int i = 0; i < NPH; i++) {
            float u = us[tid * NPH + i];
            float u2 = u * u;
            uu += u2; s4 += u2 * u2;
        }
        g_invnmid[b * NHEAD + tid] = rsqrtf(0.5f * (uu * uu + s4));
    }
}

// -------------------------------- LN kernel --------------------------------
__global__ void k_ln(const float* __restrict__ x,
                     const float* __restrict__ n1w,
                     const float* __restrict__ n1b) {
    extern __shared__ float sm[];
    float* xs   = sm;                       // 128*129
    float* su   = sm + 128 * 129;
    float* swv  = su + 128;
    float* sbv  = swv + 128;
    float* sAcc = sbv + 128;

    int tid = threadIdx.x;
    int blk = blockIdx.x;
    int b   = blk >> 7;
    int p0  = (blk & 127) << 7;

    su[tid] = g_umid[b * CIN + tid];
    {
        int c = ((tid & 31) << 2) + (tid >> 5);
        swv[tid] = n1w[c];
        sbv[tid] = n1b[c];
    }
    if (tid < NHEAD) sAcc[tid] = 0.0f;

    const float* xb = x + (size_t)b * CIN * LTOT + p0;
    #pragma unroll 4
    for (int cc = 0; cc < CIN; cc++) {
        float v = xb[(size_t)cc * LTOT + tid];
        int cp = ((cc & 3) << 5) + (cc >> 2);
        xs[tid * 129 + cp] = v;
    }
    __syncthreads();

    float* row = xs + tid * 129;
    float s = 0.f, s2 = 0.f;
    #pragma unroll 8
    for (int c = 0; c < CIN; c++) { float v = row[c]; s += v; s2 += v * v; }
    float mu   = s  * (1.0f / 128.0f);
    float var  = s2 * (1.0f / 128.0f) - mu * mu;
    float rstd = rsqrtf(var + 1e-5f);

    int gp = b * LTOT + p0 + tid;
    #pragma unroll
    for (int h = 0; h < NHEAD; h++) {
        float duv = 0.f, dvv = 0.f, suv = 0.f, sv4 = 0.f;
        #pragma unroll 8
        for (int i = 0; i < NPH; i++) {
            int c = h * NPH + i;
            float v = (row[c] - mu) * rstd * swv[c] + sbv[c];
            row[c] = v;
            float u  = su[c];
            float uv = u * v;
            float v2 = v * v;
            duv += uv; dvv += v2; suv += uv * uv; sv4 += v2 * v2;
        }
        float ny2   = 0.5f * (dvv * dvv + sv4);
        float logit = 0.5f * (duv * duv + suv) * rsqrtf(ny2) * g_invnmid[b * NHEAD + h];
        float e = expf(logit);
        g_e[gp * NHEAD + h] = e;
        float we = e;
        #pragma unroll
        for (int o = 16; o; o >>= 1) we += __shfl_xor_sync(0xffffffffu, we, o);
        if ((tid & 31) == 0) atomicAdd(&sAcc[h], we);
    }
    __syncthreads();
    if (tid < NHEAD) atomicAdd(&g_sumexp[b * NHEAD + tid], sAcc[tid]);

    float* tb = g_t + (size_t)b * CIN * LTOT + p0;
    #pragma unroll 4
    for (int c = 0; c < CIN; c++) {
        tb[(size_t)c * LTOT + tid] = xs[tid * 129 + c];
    }
}

// ------------------------------- main kernel -------------------------------
// 128 pos x 64 out per block, 512 threads (16 warps).
// Warp w: m-tile (w&7) [16 pos], n-half (w>>3) [32 n = 4 n8 tiles].
__global__ __launch_bounds__(512, 1)
void k_main(const float* __restrict__ dr_b,  const float* __restrict__ n2w,
            const float* __restrict__ n2b,   const float* __restrict__ fc1_b,
            float* __restrict__ out) {
    extern __shared__ float sm[];
    float*  sT  = sm + FT;
    float*  sPF = sm + FPF;
    float*  sB  = sm + FB;
    float*  sS  = sm + FS;
    float*  sP  = sm + FP;
    uchar2* sIJ = (uchar2*)(sm + FIJ);

    int tid  = threadIdx.x;
    int lane = tid & 31, w = tid >> 5;
    int gp0  = blockIdx.x << 7;
    int b    = gp0 >> 14;
    int p0   = gp0 & (LTOT - 1);

    // stage scales sqrt(L*attn), ij table, params
    {
        int pos = tid >> 2, h = tid & 3;
        float e = g_e[(gp0 + pos) * NHEAD + h];
        sS[tid] = sqrtf(16384.0f * e / g_sumexp[b * NHEAD + h]);
    }
    for (int idx = tid; idx < CPOOL / 2; idx += 512)
        ((uint32_t*)sIJ)[idx] = ((const uint32_t*)g_ij)[idx];
    if (tid < 64) {
        sP[tid]       = dr_b[tid];
        sP[64 + tid]  = n2w[tid];
        sP[128 + tid] = n2b[tid];
        sP[192 + tid] = fc1_b[tid];
    }
    __syncthreads();

    // stage scaled t [c][pos], stride 128
    {
        const float* tb = g_t + (size_t)b * CIN * LTOT + p0;
        #pragma unroll
        for (int it = 0; it < 8; it++) {
            int idx = tid + (it << 9);
            int c = idx >> 5, p4 = (idx & 31) << 2;
            float4 v = *(const float4*)(tb + (size_t)c * LTOT + p4);
            int hb = c >> 5;
            v.x *= sS[((p4 + 0) << 2) + hb];
            v.y *= sS[((p4 + 1) << 2) + hb];
            v.z *= sS[((p4 + 2) << 2) + hb];
            v.w *= sS[((p4 + 3) << 2) + hb];
            *(float4*)(sT + (c << 7) + p4) = v;
        }
    }

    // prefetch B chunk 0 (1024 float4 / 512 thr = 2 each)
    float4 breg[2];
    {
        const float4* ws = (const float4*)g_wTk;
        #pragma unroll
        for (int i = 0; i < 2; i++) breg[i] = ws[tid + (i << 9)];
    }

    const int tig = lane & 3, gid = lane >> 2;
    const int pbase = (w & 7) << 4;      // m16 tile
    const int nbase = (w >> 3) << 5;     // 32-wide n half

    float d[4][4];
    #pragma unroll
    for (int nt = 0; nt < 4; nt++)
        #pragma unroll
        for (int q = 0; q < 4; q++) d[nt][q] = 0.f;

    __syncthreads();

    uint32_t* pfu = (uint32_t*)sPF;
    for (int g = 0; g < NCHUNK; g++) {
        int kbase = g << 6;
        // store prefetched B chunk: [k][72]
        #pragma unroll
        for (int i = 0; i < 2; i++) {
            int idx = tid + (i << 9);
            int k = idx >> 4, n4 = (idx & 15) << 2;
            *(float4*)(sB + k * 72 + n4) = breg[i];
        }
        // build pf rows: 4 rows per warp, full 128-pos row per lane-pass
        #pragma unroll
        for (int rr = 0; rr < 4; rr++) {
            int rw = (w << 2) + rr;
            uchar2 ij = sIJ[kbase + rw];
            const float* ti = sT + ((int)ij.x << 7);
            const float* tj = sT + ((int)ij.y << 7);
            int p4 = lane << 2;
            float4 a4 = *(const float4*)(ti + p4);
            float4 b4 = *(const float4*)(tj + p4);
            uint4 r;
            r.x = cvt_tf32(a4.x * b4.x);
            r.y = cvt_tf32(a4.y * b4.y);
            r.z = cvt_tf32(a4.z * b4.z);
            r.w = cvt_tf32(a4.w * b4.w);
            *(uint4*)(pfu + rw * 136 + p4) = r;
        }
        __syncthreads();
        // prefetch next B chunk during mma
        if (g + 1 < NCHUNK) {
            const float4* ws = (const float4*)(g_wTk + (kbase + 64) * DIMO);
            #pragma unroll
            for (int i = 0; i < 2; i++) breg[i] = ws[tid + (i << 9)];
        }
        // mma over 8 k8 steps
        #pragma unroll
        for (int kk = 0; kk < 8; kk++) {
            int k0 = kk << 3;
            uint32_t a[4];
            int pr = pbase + gid;
            a[0] = pfu[(k0 + tig) * 136 + pr];
            a[1] = pfu[(k0 + tig) * 136 + pr + 8];
            a[2] = pfu[(k0 + 4 + tig) * 136 + pr];
            a[3] = pfu[(k0 + 4 + tig) * 136 + pr + 8];
            uint32_t bb[4][2];
            #pragma unroll
            for (int nt = 0; nt < 4; nt++) {
                int nc = nbase + (nt << 3) + gid;
                bb[nt][0] = __float_as_uint(sB[(k0 + tig) * 72 + nc]);
                bb[nt][1] = __float_as_uint(sB[(k0 + 4 + tig) * 72 + nc]);
            }
            #pragma unroll
            for (int nt = 0; nt < 4; nt++)
                mma8(d[nt], a, bb[nt]);
        }
        __syncthreads();
    }

    // ---- epilogue ----
    // zt[pos][68] occupies the pf region (exactly 8704 floats)
    float* zt = sPF;
    {
        int r0 = pbase + gid;
        #pragma unroll
        for (int nt = 0; nt < 4; nt++) {
            int col = nbase + (nt << 3) + (tig << 1);
            zt[r0 * 68 + col]           = d[nt][0] + sP[col];
            zt[r0 * 68 + col + 1]       = d[nt][1] + sP[col + 1];
            zt[(r0 + 8) * 68 + col]     = d[nt][2] + sP[col];
            zt[(r0 + 8) * 68 + col + 1] = d[nt][3] + sP[col + 1];
        }
    }
    // stage fc1T into t region: sF[c][68]; zo later at sT+4400 [o][132]
    float* sF = sT;
    float* zo = sT + 4400;
    #pragma unroll
    for (int it = 0; it < 8; it++) {
        int idx = tid + (it << 9);
        sF[(idx >> 6) * 68 + (idx & 63)] = g_fc1T[idx];
    }
    __syncthreads();

    // LayerNorm over 64 channels: 4 threads per position
    {
        int pos = tid >> 2, q = tid & 3;
        float* zr = zt + pos * 68 + (q << 4);
        float s = 0.f, s2 = 0.f;
        #pragma unroll
        for (int c = 0; c < 16; c++) { float v = zr[c]; s += v; s2 += v * v; }
        s  += __shfl_xor_sync(0xffffffffu, s, 1);
        s2 += __shfl_xor_sync(0xffffffffu, s2, 1);
        s  += __shfl_xor_sync(0xffffffffu, s, 2);
        s2 += __shfl_xor_sync(0xffffffffu, s2, 2);
        float mu   = s  * (1.0f / 64.0f);
        float var  = s2 * (1.0f / 64.0f) - mu * mu;
        float rstd = rsqrtf(var + 1e-5f);
        #pragma unroll
        for (int c = 0; c < 16; c++) {
            int cc = (q << 4) + c;
            zr[c] = (zr[c] - mu) * rstd * sP[64 + cc] + sP[128 + cc];
        }
    }
    __syncthreads();

    // fc1 (64x64) + GELU: thread tile 4 pos x 4 out
    {
        int tx = tid & 15, ty = tid >> 4;
        int ob = tx << 2, pb = ty << 2;
        float a2[4][4];
        #pragma unroll
        for (int r = 0; r < 4; r++)
            #pragma unroll
            for (int j = 0; j < 4; j++) a2[r][j] = 0.f;
        #pragma unroll 8
        for (int c = 0; c < DIMO; c++) {
            float4 f = *(const float4*)(sF + c * 68 + ob);
            #pragma unroll
            for (int r = 0; r < 4; r++) {
                float z = zt[(pb + r) * 68 + c];
                a2[r][0] += z * f.x; a2[r][1] += z * f.y;
                a2[r][2] += z * f.z; a2[r][3] += z * f.w;
            }
        }
        #pragma unroll
        for (int r = 0; r < 4; r++)
            #pragma unroll
            for (int j = 0; j < 4; j++) {
                float v = a2[r][j] + sP[192 + ob + j];
                v = 0.5f * v * (1.0f + erff(v * 0.70710678118654752f));
                zo[(ob + j) * 132 + pb + r] = v;
            }
    }
    __syncthreads();

    // coalesced store
    {
        float* ob = out + (size_t)b * DIMO * LTOT + p0;
        #pragma unroll
        for (int it = 0; it < 16; it++) {
            int idx = tid + (it << 9);
            int o = idx >> 7, pos = idx & 127;
            ob[(size_t)o * LTOT + pos] = zo[o * 132 + pos];
        }
    }
}

// ------------------------------- launch -----------------------------------
extern "C" void kernel_launch(void* const* d_in, const int* in_sizes, int n_in,
                              void* d_out, int out_size) {
    const float* x    = (const float*)d_in[0];
    const float* n1w  = (const float*)d_in[1];
    const float* n1b  = (const float*)d_in[2];
    const float* drw  = (const float*)d_in[3];
    const float* drb  = (const float*)d_in[4];
    const float* n2w  = (const float*)d_in[5];
    const float* n2b  = (const float*)d_in[6];
    const float* f1w  = (const float*)d_in[7];
    const float* f1b  = (const float*)d_in[8];
    float* out = (float*)d_out;

    const int SMEM_LN   = (128 * 129 + 3 * 128 + 4) * 4;   // 67600
    const int SMEM_MAIN = FTOT * 4;                        // 126080

    cudaFuncSetAttribute(k_ln,   cudaFuncAttributeMaxDynamicSharedMemorySize, SMEM_LN);
    cudaFuncSetAttribute(k_main, cudaFuncAttributeMaxDynamicSharedMemorySize, SMEM_MAIN);

    k_init<<<64, 256>>>(drw, f1w);
    k_mid<<<BATCH, 128>>>(x, n1w, n1b);
    k_ln<<<(BATCH * LTOT) / 128, 128, SMEM_LN>>>(x, n1w, n1b);
    k_main<<<(BATCH * LTOT) / 128, 512, SMEM_MAIN>>>(drb, n2w, n2b, f1b, out);
}

// round 13
// speedup vs baseline: 1.0752x; 1.0752x over previous
#include <cuda_runtime.h>
#include <math.h>
#include <stdint.h>

// ---------------------------------------------------------------------------
// SPFBlock fused kernel v7, sm_103 (portable PTX) — mma.sync m16n8k8 tf32.
// v7 = v5 tile shape (2m x 4n per warp, 512 MACs/LDS) + 16 warps via k-split:
// warps w and w+8 own the same output tile, each does half the k8-steps per
// chunk; private accumulators merged once in smem at the end.
// ---------------------------------------------------------------------------

#define BATCH   4
#define CIN     128
#define LTOT    16384
#define NHEAD   4
#define NPH     32
#define MTRI    528
#define CPOOL   2112
#define DIMO    64
#define NCHUNK  33              // 33 * 64 = 2112

// smem float offsets (k_main)
#define FT      0               // t tile [128c][128p]              16384
#define FPF     16384           // pf [64k][136] (later zt[128][68])  8704
#define FB      25088           // B  [64k][72]                       4608
#define FS      29696           // scales 512
#define FP      30208           // params 256
#define FIJ     30464           // ij table 4224 B = 1056 floats
#define FTOT    31520           // 126080 bytes

// ------------------------- device scratch (static) -------------------------
__device__ float g_t[BATCH * CIN * LTOT];       // shuffled LN'd t, [b][c][pos]
__device__ float g_e[BATCH * LTOT * NHEAD];     // exp(logit)
__device__ float g_wTk[CPOOL * DIMO];           // dr_w, k-major, tf32-rounded
__device__ float g_fc1T[DIMO * DIMO];           // fc1_w transposed [c][j]
__device__ float g_umid[BATCH * CIN];
__device__ float g_invnmid[BATCH * NHEAD];
__device__ float g_sumexp[BATCH * NHEAD];
__device__ uchar2 g_ij[CPOOL];

// ------------------------------ PTX helpers --------------------------------
__device__ __forceinline__ uint32_t cvt_tf32(float x) {
    uint32_t r;
    asm("cvt.rna.tf32.f32 %0, %1;" : "=r"(r) : "f"(x));
    return r;
}
__device__ __forceinline__ void mma8(float* d, const uint32_t* a, const uint32_t* b) {
    asm volatile(
        "mma.sync.aligned.m16n8k8.row.col.f32.tf32.tf32.f32 "
        "{%0,%1,%2,%3}, {%4,%5,%6,%7}, {%8,%9}, {%0,%1,%2,%3};"
        : "+f"(d[0]), "+f"(d[1]), "+f"(d[2]), "+f"(d[3])
        : "r"(a[0]), "r"(a[1]), "r"(a[2]), "r"(a[3]), "r"(b[0]), "r"(b[1]));
}

// ------------------------------- init kernel -------------------------------
__global__ void k_init(const float* __restrict__ dr_w,
                       const float* __restrict__ fc1_w) {
    int tid = blockIdx.x * blockDim.x + threadIdx.x;
    int nth = gridDim.x * blockDim.x;
    for (int idx = tid; idx < CPOOL * DIMO; idx += nth) {
        int k = idx >> 6, o = idx & 63;
        g_wTk[idx] = __uint_as_float(cvt_tf32(dr_w[o * CPOOL + k]));
    }
    for (int idx = tid; idx < DIMO * DIMO; idx += nth) {
        int c = idx >> 6, j = idx & 63;
        g_fc1T[idx] = fc1_w[j * DIMO + c];
    }
    if (blockIdx.x == 0) {
        for (int m = threadIdx.x; m < MTRI; m += blockDim.x) {
            int i = 0, off = 0;
            while (off + (NPH - i) <= m) { off += NPH - i; i++; }
            int j = i + (m - off);
            #pragma unroll
            for (int h = 0; h < NHEAD; h++) {
                uchar2 v;
                v.x = (unsigned char)(h * NPH + i);
                v.y = (unsigned char)(h * NPH + j);
                g_ij[h * MTRI + m] = v;
            }
        }
        if (threadIdx.x < BATCH * NHEAD) g_sumexp[threadIdx.x] = 0.0f;
    }
}

// ------------------------------- mid kernel --------------------------------
__global__ void k_mid(const float* __restrict__ x,
                      const float* __restrict__ n1w,
                      const float* __restrict__ n1b) {
    __shared__ float red[CIN];
    __shared__ float us[CIN];
    int b = blockIdx.x, tid = threadIdx.x;
    float v = x[((size_t)b * CIN + tid) * LTOT + (LTOT / 2)];
    red[tid] = v;
    __syncthreads();
    for (int o = 64; o; o >>= 1) { if (tid < o) red[tid] += red[tid + o]; __syncthreads(); }
    float mu = red[0] * (1.0f / 128.0f);
    __syncthreads();
    red[tid] = v * v;
    __syncthreads();
    for (int o = 64; o; o >>= 1) { if (tid < o) red[tid] += red[tid + o]; __syncthreads(); }
    float var = red[0] * (1.0f / 128.0f) - mu * mu;
    float rstd = rsqrtf(var + 1e-5f);
    float xn = (v - mu) * rstd * n1w[tid] + n1b[tid];
    int cp = ((tid & 3) << 5) + (tid >> 2);
    us[cp] = xn;
    g_umid[b * CIN + cp] = xn;
    __syncthreads();
    if (tid < NHEAD) {
        float uu = 0.f, s4 = 0.f;
        #pragma unroll
        for (int i = 0; i < NPH; i++) {
            float u = us[tid * NPH + i];
            float u2 = u * u;
            uu += u2; s4 += u2 * u2;
        }
        g_invnmid[b * NHEAD + tid] = rsqrtf(0.5f * (uu * uu + s4));
    }
}

// -------------------------------- LN kernel --------------------------------
__global__ void k_ln(const float* __restrict__ x,
                     const float* __restrict__ n1w,
                     const float* __restrict__ n1b) {
    extern __shared__ float sm[];
    float* xs   = sm;                       // 128*129
    float* su   = sm + 128 * 129;
    float* swv  = su + 128;
    float* sbv  = swv + 128;
    float* sAcc = sbv + 128;

    int tid = threadIdx.x;
    int blk = blockIdx.x;
    int b   = blk >> 7;
    int p0  = (blk & 127) << 7;

    su[tid] = g_umid[b * CIN + tid];
    {
        int c = ((tid & 31) << 2) + (tid >> 5);
        swv[tid] = n1w[c];
        sbv[tid] = n1b[c];
    }
    if (tid < NHEAD) sAcc[tid] = 0.0f;

    const float* xb = x + (size_t)b * CIN * LTOT + p0;
    #pragma unroll 4
    for (int cc = 0; cc < CIN; cc++) {
        float v = xb[(size_t)cc * LTOT + tid];
        int cp = ((cc & 3) << 5) + (cc >> 2);
        xs[tid * 129 + cp] = v;
    }
    __syncthreads();

    float* row = xs + tid * 129;
    float s = 0.f, s2 = 0.f;
    #pragma unroll 8
    for (int c = 0; c < CIN; c++) { float v = row[c]; s += v; s2 += v * v; }
    float mu   = s  * (1.0f / 128.0f);
    float var  = s2 * (1.0f / 128.0f) - mu * mu;
    float rstd = rsqrtf(var + 1e-5f);

    int gp = b * LTOT + p0 + tid;
    #pragma unroll
    for (int h = 0; h < NHEAD; h++) {
        float duv = 0.f, dvv = 0.f, suv = 0.f, sv4 = 0.f;
        #pragma unroll 8
        for (int i = 0; i < NPH; i++) {
            int c = h * NPH + i;
            float v = (row[c] - mu) * rstd * swv[c] + sbv[c];
            row[c] = v;
            float u  = su[c];
            float uv = u * v;
            float v2 = v * v;
            duv += uv; dvv += v2; suv += uv * uv; sv4 += v2 * v2;
        }
        float ny2   = 0.5f * (dvv * dvv + sv4);
        float logit = 0.5f * (duv * duv + suv) * rsqrtf(ny2) * g_invnmid[b * NHEAD + h];
        float e = expf(logit);
        g_e[gp * NHEAD + h] = e;
        float we = e;
        #pragma unroll
        for (int o = 16; o; o >>= 1) we += __shfl_xor_sync(0xffffffffu, we, o);
        if ((tid & 31) == 0) atomicAdd(&sAcc[h], we);
    }
    __syncthreads();
    if (tid < NHEAD) atomicAdd(&g_sumexp[b * NHEAD + tid], sAcc[tid]);

    float* tb = g_t + (size_t)b * CIN * LTOT + p0;
    #pragma unroll 4
    for (int c = 0; c < CIN; c++) {
        tb[(size_t)c * LTOT + tid] = xs[tid * 129 + c];
    }
}

// ------------------------------- main kernel -------------------------------
// 128 pos x 64 out per block, 512 threads (16 warps).
// Warp w: tile set of w&7 (2 m16-tiles x 4 n8-tiles), k-half = w>>3.
__global__ __launch_bounds__(512, 1)
void k_main(const float* __restrict__ dr_b,  const float* __restrict__ n2w,
            const float* __restrict__ n2b,   const float* __restrict__ fc1_b,
            float* __restrict__ out) {
    extern __shared__ float sm[];
    float*  sT  = sm + FT;
    float*  sPF = sm + FPF;
    float*  sB  = sm + FB;
    float*  sS  = sm + FS;
    float*  sP  = sm + FP;
    uchar2* sIJ = (uchar2*)(sm + FIJ);

    int tid  = threadIdx.x;
    int lane = tid & 31, w = tid >> 5;
    int gp0  = blockIdx.x << 7;
    int b    = gp0 >> 14;
    int p0   = gp0 & (LTOT - 1);

    // stage scales sqrt(L*attn), ij table, params
    {
        int pos = tid >> 2, h = tid & 3;
        float e = g_e[(gp0 + pos) * NHEAD + h];
        sS[tid] = sqrtf(16384.0f * e / g_sumexp[b * NHEAD + h]);
    }
    for (int idx = tid; idx < CPOOL / 2; idx += 512)
        ((uint32_t*)sIJ)[idx] = ((const uint32_t*)g_ij)[idx];
    if (tid < 64) {
        sP[tid]       = dr_b[tid];
        sP[64 + tid]  = n2w[tid];
        sP[128 + tid] = n2b[tid];
        sP[192 + tid] = fc1_b[tid];
    }
    __syncthreads();

    // stage scaled t [c][pos], stride 128
    {
        const float* tb = g_t + (size_t)b * CIN * LTOT + p0;
        #pragma unroll
        for (int it = 0; it < 8; it++) {
            int idx = tid + (it << 9);
            int c = idx >> 5, p4 = (idx & 31) << 2;
            float4 v = *(const float4*)(tb + (size_t)c * LTOT + p4);
            int hb = c >> 5;
            v.x *= sS[((p4 + 0) << 2) + hb];
            v.y *= sS[((p4 + 1) << 2) + hb];
            v.z *= sS[((p4 + 2) << 2) + hb];
            v.w *= sS[((p4 + 3) << 2) + hb];
            *(float4*)(sT + (c << 7) + p4) = v;
        }
    }

    // prefetch B chunk 0 (1024 float4 / 512 thr = 2 each)
    float4 breg[2];
    {
        const float4* ws = (const float4*)g_wTk;
        #pragma unroll
        for (int i = 0; i < 2; i++) breg[i] = ws[tid + (i << 9)];
    }

    const int tig  = lane & 3, gid = lane >> 2;
    const int w7   = w & 7;
    const int ksel = w >> 3;             // 0: k-steps 0-3, 1: k-steps 4-7
    const int pbase = (w7 & 3) << 5;     // 2 m16 tiles at pbase, pbase+16
    const int nbase = (w7 >> 2) << 5;    // 4 n8 tiles

    float d[2][4][4];
    #pragma unroll
    for (int mt = 0; mt < 2; mt++)
        #pragma unroll
        for (int nt = 0; nt < 4; nt++)
            #pragma unroll
            for (int q = 0; q < 4; q++) d[mt][nt][q] = 0.f;

    __syncthreads();

    uint32_t* pfu = (uint32_t*)sPF;
    for (int g = 0; g < NCHUNK; g++) {
        int kbase = g << 6;
        // store prefetched B chunk: [k][72]
        #pragma unroll
        for (int i = 0; i < 2; i++) {
            int idx = tid + (i << 9);
            int k = idx >> 4, n4 = (idx & 15) << 2;
            *(float4*)(sB + k * 72 + n4) = breg[i];
        }
        // build pf rows: 4 rows per warp, full 128-pos row per lane-pass
        #pragma unroll
        for (int rr = 0; rr < 4; rr++) {
            int rw = (w << 2) + rr;
            uchar2 ij = sIJ[kbase + rw];
            const float* ti = sT + ((int)ij.x << 7);
            const float* tj = sT + ((int)ij.y << 7);
            int p4 = lane << 2;
            float4 a4 = *(const float4*)(ti + p4);
            float4 b4 = *(const float4*)(tj + p4);
            uint4 r;
            r.x = cvt_tf32(a4.x * b4.x);
            r.y = cvt_tf32(a4.y * b4.y);
            r.z = cvt_tf32(a4.z * b4.z);
            r.w = cvt_tf32(a4.w * b4.w);
            *(uint4*)(pfu + rw * 136 + p4) = r;
        }
        __syncthreads();
        // prefetch next B chunk during mma
        if (g + 1 < NCHUNK) {
            const float4* ws = (const float4*)(g_wTk + (kbase + 64) * DIMO);
            #pragma unroll
            for (int i = 0; i < 2; i++) breg[i] = ws[tid + (i << 9)];
        }
        // mma over this warp's 4 k8 steps
        #pragma unroll
        for (int kk = 0; kk < 4; kk++) {
            int k0 = (kk + (ksel << 2)) << 3;
            uint32_t a[2][4];
            #pragma unroll
            for (int mt = 0; mt < 2; mt++) {
                int pr = pbase + (mt << 4) + gid;
                a[mt][0] = pfu[(k0 + tig) * 136 + pr];
                a[mt][1] = pfu[(k0 + tig) * 136 + pr + 8];
                a[mt][2] = pfu[(k0 + 4 + tig) * 136 + pr];
                a[mt][3] = pfu[(k0 + 4 + tig) * 136 + pr + 8];
            }
            uint32_t bb[4][2];
            #pragma unroll
            for (int nt = 0; nt < 4; nt++) {
                int nc = nbase + (nt << 3) + gid;
                bb[nt][0] = __float_as_uint(sB[(k0 + tig) * 72 + nc]);
                bb[nt][1] = __float_as_uint(sB[(k0 + 4 + tig) * 72 + nc]);
            }
            #pragma unroll
            for (int mt = 0; mt < 2; mt++)
                #pragma unroll
                for (int nt = 0; nt < 4; nt++)
                    mma8(d[mt][nt], a[mt], bb[nt]);
        }
        __syncthreads();
    }

    // ---- merge k-halves into zt[pos][68] (pf region) ----
    float* zt = sPF;
    if (ksel == 1) {
        #pragma unroll
        for (int mt = 0; mt < 2; mt++) {
            int r0 = pbase + (mt << 4) + gid;
            #pragma unroll
            for (int nt = 0; nt < 4; nt++) {
                int col = nbase + (nt << 3) + (tig << 1);
                zt[r0 * 68 + col]           = d[mt][nt][0];
                zt[r0 * 68 + col + 1]       = d[mt][nt][1];
                zt[(r0 + 8) * 68 + col]     = d[mt][nt][2];
                zt[(r0 + 8) * 68 + col + 1] = d[mt][nt][3];
            }
        }
    }
    // stage fc1T into t region: sF[c][68]; zo later at sT+4400 [o][132]
    float* sF = sT;
    float* zo = sT + 4400;
    #pragma unroll
    for (int it = 0; it < 8; it++) {
        int idx = tid + (it << 9);
        sF[(idx >> 6) * 68 + (idx & 63)] = g_fc1T[idx];
    }
    __syncthreads();
    if (ksel == 0) {
        #pragma unroll
        for (int mt = 0; mt < 2; mt++) {
            int r0 = pbase + (mt << 4) + gid;
            #pragma unroll
            for (int nt = 0; nt < 4; nt++) {
                int col = nbase + (nt << 3) + (tig << 1);
                zt[r0 * 68 + col]           += d[mt][nt][0] + sP[col];
                zt[r0 * 68 + col + 1]       += d[mt][nt][1] + sP[col + 1];
                zt[(r0 + 8) * 68 + col]     += d[mt][nt][2] + sP[col];
                zt[(r0 + 8) * 68 + col + 1] += d[mt][nt][3] + sP[col + 1];
            }
        }
    }
    __syncthreads();

    // LayerNorm over 64 channels: 4 threads per position
    {
        int pos = tid >> 2, q = tid & 3;
        float* zr = zt + pos * 68 + (q << 4);
        float s = 0.f, s2 = 0.f;
        #pragma unroll
        for (int c = 0; c < 16; c++) { float v = zr[c]; s += v; s2 += v * v; }
        s  += __shfl_xor_sync(0xffffffffu, s, 1);
        s2 += __shfl_xor_sync(0xffffffffu, s2, 1);
        s  += __shfl_xor_sync(0xffffffffu, s, 2);
        s2 += __shfl_xor_sync(0xffffffffu, s2, 2);
        float mu   = s  * (1.0f / 64.0f);
        float var  = s2 * (1.0f / 64.0f) - mu * mu;
        float rstd = rsqrtf(var + 1e-5f);
        #pragma unroll
        for (int c = 0; c < 16; c++) {
            int cc = (q << 4) + c;
            zr[c] = (zr[c] - mu) * rstd * sP[64 + cc] + sP[128 + cc];
        }
    }
    __syncthreads();

    // fc1 (64x64) + GELU: thread tile 4 pos x 4 out
    {
        int tx = tid & 15, ty = tid >> 4;
        int ob = tx << 2, pb = ty << 2;
        float a2[4][4];
        #pragma unroll
        for (int r = 0; r < 4; r++)
            #pragma unroll
            for (int j = 0; j < 4; j++) a2[r][j] = 0.f;
        #pragma unroll 8
        for (int c = 0; c < DIMO; c++) {
            float4 f = *(const float4*)(sF + c * 68 + ob);
            #pragma unroll
            for (int r = 0; r < 4; r++) {
                float z = zt[(pb + r) * 68 + c];
                a2[r][0] += z * f.x; a2[r][1] += z * f.y;
                a2[r][2] += z * f.z; a2[r][3] += z * f.w;
            }
        }
        #pragma unroll
        for (int r = 0; r < 4; r++)
            #pragma unroll
            for (int j = 0; j < 4; j++) {
                float v = a2[r][j] + sP[192 + ob + j];
                v = 0.5f * v * (1.0f + erff(v * 0.70710678118654752f));
                zo[(ob + j) * 132 + pb + r] = v;
            }
    }
    __syncthreads();

    // coalesced store
    {
        float* ob = out + (size_t)b * DIMO * LTOT + p0;
        #pragma unroll
        for (int it = 0; it < 16; it++) {
            int idx = tid + (it << 9);
            int o = idx >> 7, pos = idx & 127;
            ob[(size_t)o * LTOT + pos] = zo[o * 132 + pos];
        }
    }
}

// ------------------------------- launch -----------------------------------
extern "C" void kernel_launch(void* const* d_in, const int* in_sizes, int n_in,
                              void* d_out, int out_size) {
    const float* x    = (const float*)d_in[0];
    const float* n1w  = (const float*)d_in[1];
    const float* n1b  = (const float*)d_in[2];
    const float* drw  = (const float*)d_in[3];
    const float* drb  = (const float*)d_in[4];
    const float* n2w  = (const float*)d_in[5];
    const float* n2b  = (const float*)d_in[6];
    const float* f1w  = (const float*)d_in[7];
    const float* f1b  = (const float*)d_in[8];
    float* out = (float*)d_out;

    const int SMEM_LN   = (128 * 129 + 3 * 128 + 4) * 4;   // 67600
    const int SMEM_MAIN = FTOT * 4;                        // 126080

    cudaFuncSetAttribute(k_ln,   cudaFuncAttributeMaxDynamicSharedMemorySize, SMEM_LN);
    cudaFuncSetAttribute(k_main, cudaFuncAttributeMaxDynamicSharedMemorySize, SMEM_MAIN);

    k_init<<<64, 256>>>(drw, f1w);
    k_mid<<<BATCH, 128>>>(x, n1w, n1b);
    k_ln<<<(BATCH * LTOT) / 128, 128, SMEM_LN>>>(x, n1w, n1b);
    k_main<<<(BATCH * LTOT) / 128, 512, SMEM_MAIN>>>(drb, n2w, n2b, f1b, out);
}

// round 14
// speedup vs baseline: 1.1022x; 1.0251x over previous
#include <cuda_runtime.h>
#include <math.h>
#include <stdint.h>

// ---------------------------------------------------------------------------
// SPFBlock fused kernel v8, sm_103 (portable PTX) — mma.sync m16n8k8 tf32.
// v8 = v7 (2m x 4n x k-split warp tiles) + double-buffered pf/B chunks:
// one barrier per chunk; build of chunk g+1 overlaps mma of chunk g.
// ---------------------------------------------------------------------------

#define BATCH   4
#define CIN     128
#define LTOT    16384
#define NHEAD   4
#define NPH     32
#define MTRI    528
#define CPOOL   2112
#define DIMO    64
#define NCHUNK  33              // 33 * 64 = 2112

// smem float offsets (k_main)
#define FT      0               // t tile [128c][128p]                 16384
#define FPF     16384           // pf 2 x [64k][136]                   17408
#define FB      33792           // B  2 x [64k][72]                     9216
#define FS      43008           // scales 512
#define FP      43520           // params 256
#define FIJ     43776           // ij table 4224 B = 1056 floats
#define FTOT    44832           // 179328 bytes

#define PFBUF   8704            // floats per pf buffer
#define BBUF    4608            // floats per B buffer

// ------------------------- device scratch (static) -------------------------
__device__ float g_t[BATCH * CIN * LTOT];       // shuffled LN'd t, [b][c][pos]
__device__ float g_e[BATCH * LTOT * NHEAD];     // exp(logit)
__device__ float g_wTk[CPOOL * DIMO];           // dr_w, k-major, tf32-rounded
__device__ float g_fc1T[DIMO * DIMO];           // fc1_w transposed [c][j]
__device__ float g_umid[BATCH * CIN];
__device__ float g_invnmid[BATCH * NHEAD];
__device__ float g_sumexp[BATCH * NHEAD];
__device__ uchar2 g_ij[CPOOL];

// ------------------------------ PTX helpers --------------------------------
__device__ __forceinline__ uint32_t cvt_tf32(float x) {
    uint32_t r;
    asm("cvt.rna.tf32.f32 %0, %1;" : "=r"(r) : "f"(x));
    return r;
}
__device__ __forceinline__ void mma8(float* d, const uint32_t* a, const uint32_t* b) {
    asm volatile(
        "mma.sync.aligned.m16n8k8.row.col.f32.tf32.tf32.f32 "
        "{%0,%1,%2,%3}, {%4,%5,%6,%7}, {%8,%9}, {%0,%1,%2,%3};"
        : "+f"(d[0]), "+f"(d[1]), "+f"(d[2]), "+f"(d[3])
        : "r"(a[0]), "r"(a[1]), "r"(a[2]), "r"(a[3]), "r"(b[0]), "r"(b[1]));
}

// ------------------------------- init kernel -------------------------------
__global__ void k_init(const float* __restrict__ dr_w,
                       const float* __restrict__ fc1_w) {
    int tid = blockIdx.x * blockDim.x + threadIdx.x;
    int nth = gridDim.x * blockDim.x;
    for (int idx = tid; idx < CPOOL * DIMO; idx += nth) {
        int k = idx >> 6, o = idx & 63;
        g_wTk[idx] = __uint_as_float(cvt_tf32(dr_w[o * CPOOL + k]));
    }
    for (int idx = tid; idx < DIMO * DIMO; idx += nth) {
        int c = idx >> 6, j = idx & 63;
        g_fc1T[idx] = fc1_w[j * DIMO + c];
    }
    if (blockIdx.x == 0) {
        for (int m = threadIdx.x; m < MTRI; m += blockDim.x) {
            int i = 0, off = 0;
            while (off + (NPH - i) <= m) { off += NPH - i; i++; }
            int j = i + (m - off);
            #pragma unroll
            for (int h = 0; h < NHEAD; h++) {
                uchar2 v;
                v.x = (unsigned char)(h * NPH + i);
                v.y = (unsigned char)(h * NPH + j);
                g_ij[h * MTRI + m] = v;
            }
        }
        if (threadIdx.x < BATCH * NHEAD) g_sumexp[threadIdx.x] = 0.0f;
    }
}

// ------------------------------- mid kernel --------------------------------
__global__ void k_mid(const float* __restrict__ x,
                      const float* __restrict__ n1w,
                      const float* __restrict__ n1b) {
    __shared__ float red[CIN];
    __shared__ float us[CIN];
    int b = blockIdx.x, tid = threadIdx.x;
    float v = x[((size_t)b * CIN + tid) * LTOT + (LTOT / 2)];
    red[tid] = v;
    __syncthreads();
    for (int o = 64; o; o >>= 1) { if (tid < o) red[tid] += red[tid + o]; __syncthreads(); }
    float mu = red[0] * (1.0f / 128.0f);
    __syncthreads();
    red[tid] = v * v;
    __syncthreads();
    for (int o = 64; o; o >>= 1) { if (tid < o) red[tid] += red[tid + o]; __syncthreads(); }
    float var = red[0] * (1.0f / 128.0f) - mu * mu;
    float rstd = rsqrtf(var + 1e-5f);
    float xn = (v - mu) * rstd * n1w[tid] + n1b[tid];
    int cp = ((tid & 3) << 5) + (tid >> 2);
    us[cp] = xn;
    g_umid[b * CIN + cp] = xn;
    __syncthreads();
    if (tid < NHEAD) {
        float uu = 0.f, s4 = 0.f;
        #pragma unroll
        for (int i = 0; i < NPH; i++) {
            float u = us[tid * NPH + i];
            float u2 = u * u;
            uu += u2; s4 += u2 * u2;
        }
        g_invnmid[b * NHEAD + tid] = rsqrtf(0.5f * (uu * uu + s4));
    }
}

// -------------------------------- LN kernel --------------------------------
__global__ void k_ln(const float* __restrict__ x,
                     const float* __restrict__ n1w,
                     const float* __restrict__ n1b) {
    extern __shared__ float sm[];
    float* xs   = sm;                       // 128*129
    float* su   = sm + 128 * 129;
    float* swv  = su + 128;
    float* sbv  = swv + 128;
    float* sAcc = sbv + 128;

    int tid = threadIdx.x;
    int blk = blockIdx.x;
    int b   = blk >> 7;
    int p0  = (blk & 127) << 7;

    su[tid] = g_umid[b * CIN + tid];
    {
        int c = ((tid & 31) << 2) + (tid >> 5);
        swv[tid] = n1w[c];
        sbv[tid] = n1b[c];
    }
    if (tid < NHEAD) sAcc[tid] = 0.0f;

    const float* xb = x + (size_t)b * CIN * LTOT + p0;
    #pragma unroll 4
    for (int cc = 0; cc < CIN; cc++) {
        float v = xb[(size_t)cc * LTOT + tid];
        int cp = ((cc & 3) << 5) + (cc >> 2);
        xs[tid * 129 + cp] = v;
    }
    __syncthreads();

    float* row = xs + tid * 129;
    float s = 0.f, s2 = 0.f;
    #pragma unroll 8
    for (int c = 0; c < CIN; c++) { float v = row[c]; s += v; s2 += v * v; }
    float mu   = s  * (1.0f / 128.0f);
    float var  = s2 * (1.0f / 128.0f) - mu * mu;
    float rstd = rsqrtf(var + 1e-5f);

    int gp = b * LTOT + p0 + tid;
    #pragma unroll
    for (int h = 0; h < NHEAD; h++) {
        float duv = 0.f, dvv = 0.f, suv = 0.f, sv4 = 0.f;
        #pragma unroll 8
        for (int i = 0; i < NPH; i++) {
            int c = h * NPH + i;
            float v = (row[c] - mu) * rstd * swv[c] + sbv[c];
            row[c] = v;
            float u  = su[c];
            float uv = u * v;
            float v2 = v * v;
            duv += uv; dvv += v2; suv += uv * uv; sv4 += v2 * v2;
        }
        float ny2   = 0.5f * (dvv * dvv + sv4);
        float logit = 0.5f * (duv * duv + suv) * rsqrtf(ny2) * g_invnmid[b * NHEAD + h];
        float e = expf(logit);
        g_e[gp * NHEAD + h] = e;
        float we = e;
        #pragma unroll
        for (int o = 16; o; o >>= 1) we += __shfl_xor_sync(0xffffffffu, we, o);
        if ((tid & 31) == 0) atomicAdd(&sAcc[h], we);
    }
    __syncthreads();
    if (tid < NHEAD) atomicAdd(&g_sumexp[b * NHEAD + tid], sAcc[tid]);

    float* tb = g_t + (size_t)b * CIN * LTOT + p0;
    #pragma unroll 4
    for (int c = 0; c < CIN; c++) {
        tb[(size_t)c * LTOT + tid] = xs[tid * 129 + c];
    }
}

// ------------------------------- main kernel -------------------------------
// 128 pos x 64 out per block, 512 threads (16 warps).
// Warp w: tile set w&7 (2 m16 x 4 n8), k-half w>>3. Double-buffered chunks.
__global__ __launch_bounds__(512, 1)
void k_main(const float* __restrict__ dr_b,  const float* __restrict__ n2w,
            const float* __restrict__ n2b,   const float* __restrict__ fc1_b,
            float* __restrict__ out) {
    extern __shared__ float sm[];
    float*  sT  = sm + FT;
    float*  sPF = sm + FPF;
    float*  sB  = sm + FB;
    float*  sS  = sm + FS;
    float*  sP  = sm + FP;
    uchar2* sIJ = (uchar2*)(sm + FIJ);

    int tid  = threadIdx.x;
    int lane = tid & 31, w = tid >> 5;
    int gp0  = blockIdx.x << 7;
    int b    = gp0 >> 14;
    int p0   = gp0 & (LTOT - 1);

    // stage scales sqrt(L*attn), ij table, params
    {
        int pos = tid >> 2, h = tid & 3;
        float e = g_e[(gp0 + pos) * NHEAD + h];
        sS[tid] = sqrtf(16384.0f * e / g_sumexp[b * NHEAD + h]);
    }
    for (int idx = tid; idx < CPOOL / 2; idx += 512)
        ((uint32_t*)sIJ)[idx] = ((const uint32_t*)g_ij)[idx];
    if (tid < 64) {
        sP[tid]       = dr_b[tid];
        sP[64 + tid]  = n2w[tid];
        sP[128 + tid] = n2b[tid];
        sP[192 + tid] = fc1_b[tid];
    }
    __syncthreads();

    // stage scaled t [c][pos], stride 128
    {
        const float* tb = g_t + (size_t)b * CIN * LTOT + p0;
        #pragma unroll
        for (int it = 0; it < 8; it++) {
            int idx = tid + (it << 9);
            int c = idx >> 5, p4 = (idx & 31) << 2;
            float4 v = *(const float4*)(tb + (size_t)c * LTOT + p4);
            int hb = c >> 5;
            v.x *= sS[((p4 + 0) << 2) + hb];
            v.y *= sS[((p4 + 1) << 2) + hb];
            v.z *= sS[((p4 + 2) << 2) + hb];
            v.w *= sS[((p4 + 3) << 2) + hb];
            *(float4*)(sT + (c << 7) + p4) = v;
        }
    }
    __syncthreads();

    const int tig  = lane & 3, gid = lane >> 2;
    const int w7   = w & 7;
    const int ksel = w >> 3;             // 0: k-steps 0-3, 1: k-steps 4-7
    const int pbase = (w7 & 3) << 5;     // 2 m16 tiles at pbase, pbase+16
    const int nbase = (w7 >> 2) << 5;    // 4 n8 tiles
    const int p4l   = lane << 2;

    uint32_t* pfu = (uint32_t*)sPF;

    // ---- prologue: stage B(0) + build pf(0) into buffer 0 ----
    {
        const float4* ws = (const float4*)g_wTk;
        #pragma unroll
        for (int i = 0; i < 2; i++) {
            int idx = tid + (i << 9);
            float4 v = ws[idx];
            int k = idx >> 4, n4 = (idx & 15) << 2;
            *(float4*)(sB + k * 72 + n4) = v;
        }
        #pragma unroll
        for (int rr = 0; rr < 4; rr++) {
            int rw = (w << 2) + rr;
            uchar2 ij = sIJ[rw];
            float4 a4 = *(const float4*)(sT + ((int)ij.x << 7) + p4l);
            float4 b4 = *(const float4*)(sT + ((int)ij.y << 7) + p4l);
            uint4 r;
            r.x = cvt_tf32(a4.x * b4.x);
            r.y = cvt_tf32(a4.y * b4.y);
            r.z = cvt_tf32(a4.z * b4.z);
            r.w = cvt_tf32(a4.w * b4.w);
            *(uint4*)(pfu + rw * 136 + p4l) = r;
        }
    }
    __syncthreads();

    float d[2][4][4];
    #pragma unroll
    for (int mt = 0; mt < 2; mt++)
        #pragma unroll
        for (int nt = 0; nt < 4; nt++)
            #pragma unroll
            for (int q = 0; q < 4; q++) d[mt][nt][q] = 0.f;

    // ---- main loop: one barrier per chunk ----
    for (int g = 0; g < NCHUNK; g++) {
        int cur = g & 1, nxt = cur ^ 1;
        uint32_t* pfc = pfu + cur * PFBUF;
        float*    sBc = sB  + cur * BBUF;
        bool more = (g + 1 < NCHUNK);

        // 1. issue LDG for B(g+1)
        float4 breg0, breg1;
        if (more) {
            const float4* ws = (const float4*)(g_wTk + (g + 1) * 64 * DIMO);
            breg0 = ws[tid];
            breg1 = ws[tid + 512];
        }

        // 2. build pf(g+1) into nxt buffer (overlaps mma below in issue order)
        if (more) {
            int kbase = (g + 1) << 6;
            uint32_t* pfn = pfu + nxt * PFBUF;
            #pragma unroll
            for (int rr = 0; rr < 4; rr++) {
                int rw = (w << 2) + rr;
                uchar2 ij = sIJ[kbase + rw];
                float4 a4 = *(const float4*)(sT + ((int)ij.x << 7) + p4l);
                float4 b4 = *(const float4*)(sT + ((int)ij.y << 7) + p4l);
                uint4 r;
                r.x = cvt_tf32(a4.x * b4.x);
                r.y = cvt_tf32(a4.y * b4.y);
                r.z = cvt_tf32(a4.z * b4.z);
                r.w = cvt_tf32(a4.w * b4.w);
                *(uint4*)(pfn + rw * 136 + p4l) = r;
            }
        }

        // 3. mma over this warp's 4 k8 steps of chunk g
        #pragma unroll
        for (int kk = 0; kk < 4; kk++) {
            int k0 = (kk + (ksel << 2)) << 3;
            uint32_t a[2][4];
            #pragma unroll
            for (int mt = 0; mt < 2; mt++) {
                int pr = pbase + (mt << 4) + gid;
                a[mt][0] = pfc[(k0 + tig) * 136 + pr];
                a[mt][1] = pfc[(k0 + tig) * 136 + pr + 8];
                a[mt][2] = pfc[(k0 + 4 + tig) * 136 + pr];
                a[mt][3] = pfc[(k0 + 4 + tig) * 136 + pr + 8];
            }
            uint32_t bb[4][2];
            #pragma unroll
            for (int nt = 0; nt < 4; nt++) {
                int nc = nbase + (nt << 3) + gid;
                bb[nt][0] = __float_as_uint(sBc[(k0 + tig) * 72 + nc]);
                bb[nt][1] = __float_as_uint(sBc[(k0 + 4 + tig) * 72 + nc]);
            }
            #pragma unroll
            for (int mt = 0; mt < 2; mt++)
                #pragma unroll
                for (int nt = 0; nt < 4; nt++)
                    mma8(d[mt][nt], a[mt], bb[nt]);
        }

        // 4. store B(g+1) into nxt buffer
        if (more) {
            float* sBn = sB + nxt * BBUF;
            int k0i = tid >> 4, n40 = (tid & 15) << 2;
            *(float4*)(sBn + k0i * 72 + n40) = breg0;
            int idx1 = tid + 512;
            int k1i = idx1 >> 4, n41 = (idx1 & 15) << 2;
            *(float4*)(sBn + k1i * 72 + n41) = breg1;
        }
        __syncthreads();
    }

    // ---- merge k-halves into zt[pos][68] (pf region) ----
    float* zt = sPF;
    if (ksel == 1) {
        #pragma unroll
        for (int mt = 0; mt < 2; mt++) {
            int r0 = pbase + (mt << 4) + gid;
            #pragma unroll
            for (int nt = 0; nt < 4; nt++) {
                int col = nbase + (nt << 3) + (tig << 1);
                zt[r0 * 68 + col]           = d[mt][nt][0];
                zt[r0 * 68 + col + 1]       = d[mt][nt][1];
                zt[(r0 + 8) * 68 + col]     = d[mt][nt][2];
                zt[(r0 + 8) * 68 + col + 1] = d[mt][nt][3];
            }
        }
    }
    // stage fc1T into t region: sF[c][68]; zo later at sT+4400 [o][132]
    float* sF = sT;
    float* zo = sT + 4400;
    #pragma unroll
    for (int it = 0; it < 8; it++) {
        int idx = tid + (it << 9);
        sF[(idx >> 6) * 68 + (idx & 63)] = g_fc1T[idx];
    }
    __syncthreads();
    if (ksel == 0) {
        #pragma unroll
        for (int mt = 0; mt < 2; mt++) {
            int r0 = pbase + (mt << 4) + gid;
            #pragma unroll
            for (int nt = 0; nt < 4; nt++) {
                int col = nbase + (nt << 3) + (tig << 1);
                zt[r0 * 68 + col]           += d[mt][nt][0] + sP[col];
                zt[r0 * 68 + col + 1]       += d[mt][nt][1] + sP[col + 1];
                zt[(r0 + 8) * 68 + col]     += d[mt][nt][2] + sP[col];
                zt[(r0 + 8) * 68 + col + 1] += d[mt][nt][3] + sP[col + 1];
            }
        }
    }
    __syncthreads();

    // LayerNorm over 64 channels: 4 threads per position
    {
        int pos = tid >> 2, q = tid & 3;
        float* zr = zt + pos * 68 + (q << 4);
        float s = 0.f, s2 = 0.f;
        #pragma unroll
        for (int c = 0; c < 16; c++) { float v = zr[c]; s += v; s2 += v * v; }
        s  += __shfl_xor_sync(0xffffffffu, s, 1);
        s2 += __shfl_xor_sync(0xffffffffu, s2, 1);
        s  += __shfl_xor_sync(0xffffffffu, s, 2);
        s2 += __shfl_xor_sync(0xffffffffu, s2, 2);
        float mu   = s  * (1.0f / 64.0f);
        float var  = s2 * (1.0f / 64.0f) - mu * mu;
        float rstd = rsqrtf(var + 1e-5f);
        #pragma unroll
        for (int c = 0; c < 16; c++) {
            int cc = (q << 4) + c;
            zr[c] = (zr[c] - mu) * rstd * sP[64 + cc] + sP[128 + cc];
        }
    }
    __syncthreads();

    // fc1 (64x64) + GELU: thread tile 4 pos x 4 out
    {
        int tx = tid & 15, ty = tid >> 4;
        int ob = tx << 2, pb = ty << 2;
        float a2[4][4];
        #pragma unroll
        for (int r = 0; r < 4; r++)
            #pragma unroll
            for (int j = 0; j < 4; j++) a2[r][j] = 0.f;
        #pragma unroll 8
        for (int c = 0; c < DIMO; c++) {
            float4 f = *(const float4*)(sF + c * 68 + ob);
            #pragma unroll
            for (int r = 0; r < 4; r++) {
                float z = zt[(pb + r) * 68 + c];
                a2[r][0] += z * f.x; a2[r][1] += z * f.y;
                a2[r][2] += z * f.z; a2[r][3] += z * f.w;
            }
        }
        #pragma unroll
        for (int r = 0; r < 4; r++)
            #pragma unroll
            for (int j = 0; j < 4; j++) {
                float v = a2[r][j] + sP[192 + ob + j];
                v = 0.5f * v * (1.0f + erff(v * 0.70710678118654752f));
                zo[(ob + j) * 132 + pb + r] = v;
            }
    }
    __syncthreads();

    // coalesced store
    {
        float* ob = out + (size_t)b * DIMO * LTOT + p0;
        #pragma unroll
        for (int it = 0; it < 16; it++) {
            int idx = tid + (it << 9);
            int o = idx >> 7, pos = idx & 127;
            ob[(size_t)o * LTOT + pos] = zo[o * 132 + pos];
        }
    }
}

// ------------------------------- launch -----------------------------------
extern "C" void kernel_launch(void* const* d_in, const int* in_sizes, int n_in,
                              void* d_out, int out_size) {
    const float* x    = (const float*)d_in[0];
    const float* n1w  = (const float*)d_in[1];
    const float* n1b  = (const float*)d_in[2];
    const float* drw  = (const float*)d_in[3];
    const float* drb  = (const float*)d_in[4];
    const float* n2w  = (const float*)d_in[5];
    const float* n2b  = (const float*)d_in[6];
    const float* f1w  = (const float*)d_in[7];
    const float* f1b  = (const float*)d_in[8];
    float* out = (float*)d_out;

    const int SMEM_LN   = (128 * 129 + 3 * 128 + 4) * 4;   // 67600
    const int SMEM_MAIN = FTOT * 4;                        // 179328

    cudaFuncSetAttribute(k_ln,   cudaFuncAttributeMaxDynamicSharedMemorySize, SMEM_LN);
    cudaFuncSetAttribute(k_main, cudaFuncAttributeMaxDynamicSharedMemorySize, SMEM_MAIN);

    k_init<<<64, 256>>>(drw, f1w);
    k_mid<<<BATCH, 128>>>(x, n1w, n1b);
    k_ln<<<(BATCH * LTOT) / 128, 128, SMEM_LN>>>(x, n1w, n1b);
    k_main<<<(BATCH * LTOT) / 128, 512, SMEM_MAIN>>>(drb, n2w, n2b, f1b, out);
}

// round 15
// speedup vs baseline: 1.1481x; 1.0417x over previous
#include <cuda_runtime.h>
#include <math.h>
#include <stdint.h>

// ---------------------------------------------------------------------------
// SPFBlock fused kernel v9, sm_103 (portable PTX) — mma.sync m16n8k8 tf32.
// v9: 64-pos / 256-thread blocks at 106.5 KB smem -> 2 blocks/SM (32 warps):
// cross-block overlap of build/mma/barrier phases. B stored [n][k] (stride 68,
// conflict-free, coalesced staging from dr_w's native layout); ij via __ldg.
// ---------------------------------------------------------------------------

#define BATCH   4
#define CIN     128
#define LTOT    16384
#define NHEAD   4
#define NPH     32
#define MTRI    528
#define CPOOL   2112
#define DIMO    64
#define NCHUNK  33              // 33 * 64 = 2112
#define POSB    64              // positions per block

// smem float offsets (k_main)
#define FT      0               // t tile [128c][64p]                  8192
#define FPF     8192            // pf 2 x [64k][72]                    9216
#define FB      17408           // B  2 x [64n][68]                    8704
#define FS      26112           // scales 256
#define FP      26368           // params 256
#define FTOT    26624           // 106496 bytes

#define PFBUF   4608            // floats per pf buffer (64*72)
#define BBUF    4352            // floats per B buffer  (64*68)

// ------------------------- device scratch (static) -------------------------
__device__ float g_t[BATCH * CIN * LTOT];       // shuffled LN'd t, [b][c][pos]
__device__ float g_e[BATCH * LTOT * NHEAD];     // exp(logit)
__device__ float g_wNk[DIMO * CPOOL];           // tf32-rounded dr_w, [n][k]
__device__ float g_fc1T[DIMO * DIMO];           // fc1_w transposed [c][j]
__device__ float g_umid[BATCH * CIN];
__device__ float g_invnmid[BATCH * NHEAD];
__device__ float g_sumexp[BATCH * NHEAD];
__device__ uchar2 g_ij[CPOOL];

// ------------------------------ PTX helpers --------------------------------
__device__ __forceinline__ uint32_t cvt_tf32(float x) {
    uint32_t r;
    asm("cvt.rna.tf32.f32 %0, %1;" : "=r"(r) : "f"(x));
    return r;
}
__device__ __forceinline__ void mma8(float* d, const uint32_t* a, const uint32_t* b) {
    asm volatile(
        "mma.sync.aligned.m16n8k8.row.col.f32.tf32.tf32.f32 "
        "{%0,%1,%2,%3}, {%4,%5,%6,%7}, {%8,%9}, {%0,%1,%2,%3};"
        : "+f"(d[0]), "+f"(d[1]), "+f"(d[2]), "+f"(d[3])
        : "r"(a[0]), "r"(a[1]), "r"(a[2]), "r"(a[3]), "r"(b[0]), "r"(b[1]));
}

// ------------------------------- init kernel -------------------------------
__global__ void k_init(const float* __restrict__ dr_w,
                       const float* __restrict__ fc1_w) {
    int tid = blockIdx.x * blockDim.x + threadIdx.x;
    int nth = gridDim.x * blockDim.x;
    for (int idx = tid; idx < DIMO * CPOOL; idx += nth)
        g_wNk[idx] = __uint_as_float(cvt_tf32(dr_w[idx]));
    for (int idx = tid; idx < DIMO * DIMO; idx += nth) {
        int c = idx >> 6, j = idx & 63;
        g_fc1T[idx] = fc1_w[j * DIMO + c];
    }
    if (blockIdx.x == 0) {
        for (int m = threadIdx.x; m < MTRI; m += blockDim.x) {
            int i = 0, off = 0;
            while (off + (NPH - i) <= m) { off += NPH - i; i++; }
            int j = i + (m - off);
            #pragma unroll
            for (int h = 0; h < NHEAD; h++) {
                uchar2 v;
                v.x = (unsigned char)(h * NPH + i);
                v.y = (unsigned char)(h * NPH + j);
                g_ij[h * MTRI + m] = v;
            }
        }
        if (threadIdx.x < BATCH * NHEAD) g_sumexp[threadIdx.x] = 0.0f;
    }
}

// ------------------------------- mid kernel --------------------------------
__global__ void k_mid(const float* __restrict__ x,
                      const float* __restrict__ n1w,
                      const float* __restrict__ n1b) {
    __shared__ float red[CIN];
    __shared__ float us[CIN];
    int b = blockIdx.x, tid = threadIdx.x;
    float v = x[((size_t)b * CIN + tid) * LTOT + (LTOT / 2)];
    red[tid] = v;
    __syncthreads();
    for (int o = 64; o; o >>= 1) { if (tid < o) red[tid] += red[tid + o]; __syncthreads(); }
    float mu = red[0] * (1.0f / 128.0f);
    __syncthreads();
    red[tid] = v * v;
    __syncthreads();
    for (int o = 64; o; o >>= 1) { if (tid < o) red[tid] += red[tid + o]; __syncthreads(); }
    float var = red[0] * (1.0f / 128.0f) - mu * mu;
    float rstd = rsqrtf(var + 1e-5f);
    float xn = (v - mu) * rstd * n1w[tid] + n1b[tid];
    int cp = ((tid & 3) << 5) + (tid >> 2);
    us[cp] = xn;
    g_umid[b * CIN + cp] = xn;
    __syncthreads();
    if (tid < NHEAD) {
        float uu = 0.f, s4 = 0.f;
        #pragma unroll
        for (int i = 0; i < NPH; i++) {
            float u = us[tid * NPH + i];
            float u2 = u * u;
            uu += u2; s4 += u2 * u2;
        }
        g_invnmid[b * NHEAD + tid] = rsqrtf(0.5f * (uu * uu + s4));
    }
}

// -------------------------------- LN kernel --------------------------------
__global__ void k_ln(const float* __restrict__ x,
                     const float* __restrict__ n1w,
                     const float* __restrict__ n1b) {
    extern __shared__ float sm[];
    float* xs   = sm;                       // 128*129
    float* su   = sm + 128 * 129;
    float* swv  = su + 128;
    float* sbv  = swv + 128;
    float* sAcc = sbv + 128;

    int tid = threadIdx.x;
    int blk = blockIdx.x;
    int b   = blk >> 7;
    int p0  = (blk & 127) << 7;

    su[tid] = g_umid[b * CIN + tid];
    {
        int c = ((tid & 31) << 2) + (tid >> 5);
        swv[tid] = n1w[c];
        sbv[tid] = n1b[c];
    }
    if (tid < NHEAD) sAcc[tid] = 0.0f;

    const float* xb = x + (size_t)b * CIN * LTOT + p0;
    #pragma unroll 4
    for (int cc = 0; cc < CIN; cc++) {
        float v = xb[(size_t)cc * LTOT + tid];
        int cp = ((cc & 3) << 5) + (cc >> 2);
        xs[tid * 129 + cp] = v;
    }
    __syncthreads();

    float* row = xs + tid * 129;
    float s = 0.f, s2 = 0.f;
    #pragma unroll 8
    for (int c = 0; c < CIN; c++) { float v = row[c]; s += v; s2 += v * v; }
    float mu   = s  * (1.0f / 128.0f);
    float var  = s2 * (1.0f / 128.0f) - mu * mu;
    float rstd = rsqrtf(var + 1e-5f);

    int gp = b * LTOT + p0 + tid;
    #pragma unroll
    for (int h = 0; h < NHEAD; h++) {
        float duv = 0.f, dvv = 0.f, suv = 0.f, sv4 = 0.f;
        #pragma unroll 8
        for (int i = 0; i < NPH; i++) {
            int c = h * NPH + i;
            float v = (row[c] - mu) * rstd * swv[c] + sbv[c];
            row[c] = v;
            float u  = su[c];
            float uv = u * v;
            float v2 = v * v;
            duv += uv; dvv += v2; suv += uv * uv; sv4 += v2 * v2;
        }
        float ny2   = 0.5f * (dvv * dvv + sv4);
        float logit = 0.5f * (duv * duv + suv) * rsqrtf(ny2) * g_invnmid[b * NHEAD + h];
        float e = expf(logit);
        g_e[gp * NHEAD + h] = e;
        float we = e;
        #pragma unroll
        for (int o = 16; o; o >>= 1) we += __shfl_xor_sync(0xffffffffu, we, o);
        if ((tid & 31) == 0) atomicAdd(&sAcc[h], we);
    }
    __syncthreads();
    if (tid < NHEAD) atomicAdd(&g_sumexp[b * NHEAD + tid], sAcc[tid]);

    float* tb = g_t + (size_t)b * CIN * LTOT + p0;
    #pragma unroll 4
    for (int c = 0; c < CIN; c++) {
        tb[(size_t)c * LTOT + tid] = xs[tid * 129 + c];
    }
}

// ------------------------------- main kernel -------------------------------
// 64 pos x 64 out per block, 256 threads (8 warps), 2 blocks/SM.
// Warp w: m-group w&1 (2 m16), n-group (w>>1)&1 (4 n8), k-half w>>2.
__global__ __launch_bounds__(256, 2)
void k_main(const float* __restrict__ dr_b,  const float* __restrict__ n2w,
            const float* __restrict__ n2b,   const float* __restrict__ fc1_b,
            float* __restrict__ out) {
    extern __shared__ float sm[];
    float* sT = sm + FT;                 // [128c][64p]
    float* sB = sm + FB;                 // 2 x [64n][68k]
    float* sS = sm + FS;
    float* sP = sm + FP;
    uint32_t* pfu = (uint32_t*)(sm + FPF);   // 2 x [64k][72p]

    int tid  = threadIdx.x;
    int lane = tid & 31, w = tid >> 5;
    int gp0  = blockIdx.x << 6;
    int b    = gp0 >> 14;
    int p0   = gp0 & (LTOT - 1);

    // stage scales sqrt(L*attn) and params
    {
        int pos = tid >> 2, h = tid & 3;
        float e = g_e[(gp0 + pos) * NHEAD + h];
        sS[tid] = sqrtf(16384.0f * e / g_sumexp[b * NHEAD + h]);
    }
    if (tid < 64) {
        sP[tid]       = dr_b[tid];
        sP[64 + tid]  = n2w[tid];
        sP[128 + tid] = n2b[tid];
        sP[192 + tid] = fc1_b[tid];
    }
    __syncthreads();

    // stage scaled t [c][pos], stride 64
    {
        const float* tb = g_t + (size_t)b * CIN * LTOT + p0;
        #pragma unroll
        for (int it = 0; it < 8; it++) {
            int idx = tid + (it << 8);
            int c = idx >> 4, p4 = (idx & 15) << 2;
            float4 v = *(const float4*)(tb + (size_t)c * LTOT + p4);
            int hb = c >> 5;
            v.x *= sS[((p4 + 0) << 2) + hb];
            v.y *= sS[((p4 + 1) << 2) + hb];
            v.z *= sS[((p4 + 2) << 2) + hb];
            v.w *= sS[((p4 + 3) << 2) + hb];
            *(float4*)(sT + (c << 6) + p4) = v;
        }
    }
    __syncthreads();

    const int tig  = lane & 3, gid = lane >> 2;
    const int ksel = w >> 2;                 // 0: ksteps 0-3, 1: ksteps 4-7
    const int pbase = (w & 1) << 5;          // 2 m16 tiles at pbase, pbase+16
    const int nbase = ((w >> 1) & 1) << 5;   // 4 n8 tiles
    const int rhalf = lane >> 4;             // build: row within pass
    const int p4l   = (lane & 15) << 2;      // build: float4 pos index

    // ---- prologue: stage B(0) + build pf(0) into buffer 0 ----
    {
        #pragma unroll
        for (int i = 0; i < 4; i++) {
            int idx = tid + (i << 8);
            int n = idx >> 4, k4 = (idx & 15) << 2;
            float4 v = *(const float4*)(g_wNk + n * CPOOL + k4);
            *(float4*)(sB + n * 68 + k4) = v;
        }
        #pragma unroll
        for (int pass = 0; pass < 4; pass++) {
            int rw = (w << 3) + (pass << 1) + rhalf;
            uchar2 ij = __ldg(&g_ij[rw]);
            float4 a4 = *(const float4*)(sT + ((int)ij.x << 6) + p4l);
            float4 b4 = *(const float4*)(sT + ((int)ij.y << 6) + p4l);
            uint4 r;
            r.x = cvt_tf32(a4.x * b4.x);
            r.y = cvt_tf32(a4.y * b4.y);
            r.z = cvt_tf32(a4.z * b4.z);
            r.w = cvt_tf32(a4.w * b4.w);
            *(uint4*)(pfu + rw * 72 + p4l) = r;
        }
    }
    __syncthreads();

    float d[2][4][4];
    #pragma unroll
    for (int mt = 0; mt < 2; mt++)
        #pragma unroll
        for (int nt = 0; nt < 4; nt++)
            #pragma unroll
            for (int q = 0; q < 4; q++) d[mt][nt][q] = 0.f;

    // ---- main loop: one barrier per chunk ----
    for (int g = 0; g < NCHUNK; g++) {
        int cur = g & 1, nxt = cur ^ 1;
        uint32_t* pfc = pfu + cur * PFBUF;
        float*    sBc = sB  + cur * BBUF;
        bool more = (g + 1 < NCHUNK);

        // 1. issue LDG for B(g+1)
        float4 breg[4];
        if (more) {
            const float* wsrc = g_wNk + ((g + 1) << 6);
            #pragma unroll
            for (int i = 0; i < 4; i++) {
                int idx = tid + (i << 8);
                int n = idx >> 4, k4 = (idx & 15) << 2;
                breg[i] = *(const float4*)(wsrc + n * CPOOL + k4);
            }
        }

        // 2. build pf(g+1) into nxt buffer (overlaps mma in issue order)
        if (more) {
            int kbase = (g + 1) << 6;
            uint32_t* pfn = pfu + nxt * PFBUF;
            #pragma unroll
            for (int pass = 0; pass < 4; pass++) {
                int rw = (w << 3) + (pass << 1) + rhalf;
                uchar2 ij = __ldg(&g_ij[kbase + rw]);
                float4 a4 = *(const float4*)(sT + ((int)ij.x << 6) + p4l);
                float4 b4 = *(const float4*)(sT + ((int)ij.y << 6) + p4l);
                uint4 r;
                r.x = cvt_tf32(a4.x * b4.x);
                r.y = cvt_tf32(a4.y * b4.y);
                r.z = cvt_tf32(a4.z * b4.z);
                r.w = cvt_tf32(a4.w * b4.w);
                *(uint4*)(pfn + rw * 72 + p4l) = r;
            }
        }

        // 3. mma over this warp's 4 k8 steps of chunk g
        #pragma unroll
        for (int kk = 0; kk < 4; kk++) {
            int k0 = (kk + (ksel << 2)) << 3;
            uint32_t a[2][4];
            #pragma unroll
            for (int mt = 0; mt < 2; mt++) {
                int pr = pbase + (mt << 4) + gid;
                a[mt][0] = pfc[(k0 + tig) * 72 + pr];
                a[mt][1] = pfc[(k0 + tig) * 72 + pr + 8];
                a[mt][2] = pfc[(k0 + 4 + tig) * 72 + pr];
                a[mt][3] = pfc[(k0 + 4 + tig) * 72 + pr + 8];
            }
            uint32_t bb[4][2];
            #pragma unroll
            for (int nt = 0; nt < 4; nt++) {
                int nc = nbase + (nt << 3) + gid;
                bb[nt][0] = __float_as_uint(sBc[nc * 68 + k0 + tig]);
                bb[nt][1] = __float_as_uint(sBc[nc * 68 + k0 + 4 + tig]);
            }
            #pragma unroll
            for (int mt = 0; mt < 2; mt++)
                #pragma unroll
                for (int nt = 0; nt < 4; nt++)
                    mma8(d[mt][nt], a[mt], bb[nt]);
        }

        // 4. store B(g+1) into nxt buffer
        if (more) {
            float* sBn = sB + nxt * BBUF;
            #pragma unroll
            for (int i = 0; i < 4; i++) {
                int idx = tid + (i << 8);
                int n = idx >> 4, k4 = (idx & 15) << 2;
                *(float4*)(sBn + n * 68 + k4) = breg[i];
            }
        }
        __syncthreads();
    }

    // ---- merge k-halves into zt[pos][68] (pf region) ----
    float* zt = (float*)pfu;
    if (ksel == 1) {
        #pragma unroll
        for (int mt = 0; mt < 2; mt++) {
            int r0 = pbase + (mt << 4) + gid;
            #pragma unroll
            for (int nt = 0; nt < 4; nt++) {
                int col = nbase + (nt << 3) + (tig << 1);
                zt[r0 * 68 + col]           = d[mt][nt][0];
                zt[r0 * 68 + col + 1]       = d[mt][nt][1];
                zt[(r0 + 8) * 68 + col]     = d[mt][nt][2];
                zt[(r0 + 8) * 68 + col + 1] = d[mt][nt][3];
            }
        }
    }
    // stage fc1T into t region: sF[c][68]
    float* sF = sT;
    #pragma unroll
    for (int it = 0; it < 16; it++) {
        int idx = tid + (it << 8);
        sF[(idx >> 6) * 68 + (idx & 63)] = g_fc1T[idx];
    }
    __syncthreads();
    if (ksel == 0) {
        #pragma unroll
        for (int mt = 0; mt < 2; mt++) {
            int r0 = pbase + (mt << 4) + gid;
            #pragma unroll
            for (int nt = 0; nt < 4; nt++) {
                int col = nbase + (nt << 3) + (tig << 1);
                zt[r0 * 68 + col]           += d[mt][nt][0] + sP[col];
                zt[r0 * 68 + col + 1]       += d[mt][nt][1] + sP[col + 1];
                zt[(r0 + 8) * 68 + col]     += d[mt][nt][2] + sP[col];
                zt[(r0 + 8) * 68 + col + 1] += d[mt][nt][3] + sP[col + 1];
            }
        }
    }
    __syncthreads();

    // LayerNorm over 64 channels: 4 threads per position
    {
        int pos = tid >> 2, q = tid & 3;
        float* zr = zt + pos * 68 + (q << 4);
        float s = 0.f, s2 = 0.f;
        #pragma unroll
        for (int c = 0; c < 16; c++) { float v = zr[c]; s += v; s2 += v * v; }
        s  += __shfl_xor_sync(0xffffffffu, s, 1);
        s2 += __shfl_xor_sync(0xffffffffu, s2, 1);
        s  += __shfl_xor_sync(0xffffffffu, s, 2);
        s2 += __shfl_xor_sync(0xffffffffu, s2, 2);
        float mu   = s  * (1.0f / 64.0f);
        float var  = s2 * (1.0f / 64.0f) - mu * mu;
        float rstd = rsqrtf(var + 1e-5f);
        #pragma unroll
        for (int c = 0; c < 16; c++) {
            int cc = (q << 4) + c;
            zr[c] = (zr[c] - mu) * rstd * sP[64 + cc] + sP[128 + cc];
        }
    }
    __syncthreads();

    // fc1 (64x64) + GELU: thread tile 4 pos x 4 out; zo in B region [o][68]
    float* zo = sB;
    {
        int tx = tid & 15, ty = tid >> 4;
        int ob = tx << 2, pb = ty << 2;
        float a2[4][4];
        #pragma unroll
        for (int r = 0; r < 4; r++)
            #pragma unroll
            for (int j = 0; j < 4; j++) a2[r][j] = 0.f;
        #pragma unroll 8
        for (int c = 0; c < DIMO; c++) {
            float4 f = *(const float4*)(sF + c * 68 + ob);
            #pragma unroll
            for (int r = 0; r < 4; r++) {
                float z = zt[(pb + r) * 68 + c];
                a2[r][0] += z * f.x; a2[r][1] += z * f.y;
                a2[r][2] += z * f.z; a2[r][3] += z * f.w;
            }
        }
        #pragma unroll
        for (int r = 0; r < 4; r++)
            #pragma unroll
            for (int j = 0; j < 4; j++) {
                float v = a2[r][j] + sP[192 + ob + j];
                v = 0.5f * v * (1.0f + erff(v * 0.70710678118654752f));
                zo[(ob + j) * 68 + pb + r] = v;
            }
    }
    __syncthreads();

    // coalesced store
    {
        float* ob = out + (size_t)b * DIMO * LTOT + p0;
        #pragma unroll
        for (int it = 0; it < 16; it++) {
            int idx = tid + (it << 8);
            int o = idx >> 6, pos = idx & 63;
            ob[(size_t)o * LTOT + pos] = zo[o * 68 + pos];
        }
    }
}

// ------------------------------- launch -----------------------------------
extern "C" void kernel_launch(void* const* d_in, const int* in_sizes, int n_in,
                              void* d_out, int out_size) {
    const float* x    = (const float*)d_in[0];
    const float* n1w  = (const float*)d_in[1];
    const float* n1b  = (const float*)d_in[2];
    const float* drw  = (const float*)d_in[3];
    const float* drb  = (const float*)d_in[4];
    const float* n2w  = (const float*)d_in[5];
    const float* n2b  = (const float*)d_in[6];
    const float* f1w  = (const float*)d_in[7];
    const float* f1b  = (const float*)d_in[8];
    float* out = (float*)d_out;

    const int SMEM_LN   = (128 * 129 + 3 * 128 + 4) * 4;   // 67600
    const int SMEM_MAIN = FTOT * 4;                        // 106496

    cudaFuncSetAttribute(k_ln,   cudaFuncAttributeMaxDynamicSharedMemorySize, SMEM_LN);
    cudaFuncSetAttribute(k_main, cudaFuncAttributeMaxDynamicSharedMemorySize, SMEM_MAIN);

    k_init<<<64, 256>>>(drw, f1w);
    k_mid<<<BATCH, 128>>>(x, n1w, n1b);
    k_ln<<<(BATCH * LTOT) / 128, 128, SMEM_LN>>>(x, n1w, n1b);
    k_main<<<(BATCH * LTOT) / POSB, 256, SMEM_MAIN>>>(drb, n2w, n2b, f1b, out);
}